// round 15
// baseline (speedup 1.0000x reference)
#include <cuda_runtime.h>
#include <cuda_bf16.h>
#include <cstdint>

#define NNODES 100000
#define NEDGES 1600000
#define DIM    128
#define SCANB  1024
#define NBLK   ((NNODES + SCANB - 1) / SCANB)   // 98
#define SWROW  129                              // smem row stride (mod 32 == 1)

typedef unsigned long long u64;

// ---------------- scratch (alloc-free rule: __device__ globals) -------------
// g_deg: zero-initialized at module load; fill_kernel re-zeroes it each call.
__device__ int g_deg[NNODES];
__device__ int g_incl[NNODES];
__device__ int g_off[NNODES + 1];
__device__ int g_cur[NNODES];
__device__ int g_csr[NEDGES];
__device__ int g_bsum[128];
__device__ int g_bofs[128];

// ---------------------------------------------------------------------------
// packed fp32x2 helpers
// ---------------------------------------------------------------------------
__device__ __forceinline__ u64 ffma2(u64 a, u64 b, u64 c) {
    u64 d;
    asm("fma.rn.f32x2 %0, %1, %2, %3;" : "=l"(d) : "l"(a), "l"(b), "l"(c));
    return d;
}
__device__ __forceinline__ u64 pk2(float lo, float hi) {
    u64 r;
    asm("mov.b64 %0, {%1, %2};" : "=l"(r) : "f"(lo), "f"(hi));
    return r;
}

// ---------------------------------------------------------------------------
// CSR build
// ---------------------------------------------------------------------------
__global__ void hist_kernel(const int* __restrict__ ei) {
    int e = blockIdx.x * blockDim.x + threadIdx.x;
    if (e < NEDGES) atomicAdd(&g_deg[__ldg(ei + NEDGES + e)], 1);
}

__global__ void scan1_kernel() {
    __shared__ int sm[SCANB];
    int i = blockIdx.x * SCANB + threadIdx.x;
    int v = (i < NNODES) ? g_deg[i] : 0;
    sm[threadIdx.x] = v;
    __syncthreads();
#pragma unroll
    for (int ofs = 1; ofs < SCANB; ofs <<= 1) {
        int t = (threadIdx.x >= ofs) ? sm[threadIdx.x - ofs] : 0;
        __syncthreads();
        sm[threadIdx.x] += t;
        __syncthreads();
    }
    if (i < NNODES) g_incl[i] = sm[threadIdx.x];
    if (threadIdx.x == SCANB - 1) g_bsum[blockIdx.x] = sm[SCANB - 1];
}

__global__ void scan2_kernel() {
    __shared__ int sm[128];
    int t = threadIdx.x;
    int v = (t < NBLK) ? g_bsum[t] : 0;
    sm[t] = v;
    __syncthreads();
#pragma unroll
    for (int ofs = 1; ofs < 128; ofs <<= 1) {
        int u = (t >= ofs) ? sm[t - ofs] : 0;
        __syncthreads();
        sm[t] += u;
        __syncthreads();
    }
    if (t < NBLK) g_bofs[t] = sm[t] - v;    // exclusive
}

__global__ void scan3_kernel() {
    int i = blockIdx.x * blockDim.x + threadIdx.x;
    if (i < NNODES) {
        int off = g_incl[i] - g_deg[i] + g_bofs[i >> 10];
        g_off[i] = off;
        g_cur[i] = off;
    }
    if (i == 0) g_off[NNODES] = NEDGES;
}

__global__ void fill_kernel(const int* __restrict__ ei) {
    int e = blockIdx.x * blockDim.x + threadIdx.x;
    if (e < NEDGES) {
        int dst = __ldg(ei + NEDGES + e);
        int p = atomicAdd(&g_cur[dst], 1);
        g_csr[p] = __ldg(ei + e);
    }
    if (e < NNODES) g_deg[e] = 0;   // restore invariant for next replay
}

// ---------------------------------------------------------------------------
// FUSED GIN layer: out[n][o] = bias[o] + sum_k (x[n][k] + sum_{j in N(n)} x[j][k]) * W[o][k]
//
// One block = 64 nodes x 128 outs, 128 threads (4 warps).
// Phase 1: warps fill Ws (W, untransposed, stride 129) AND gather-aggregate
//          the 64 H rows directly into Hs (R6 warp-per-node CSR loop,
//          16 nodes/warp). No g_agg buffer at all.
// Phase 2: measured-good R9 compute: 8x8 register tile, packed f32x2 FMA.
// 2 blocks/SM -> one block's FFMA mainloop overlaps the other's gather.
// ---------------------------------------------------------------------------
__global__ __launch_bounds__(128, 2)
void gin_layer_kernel(const float* __restrict__ x,
                      const float* __restrict__ W,
                      const float* __restrict__ bias,
                      float* __restrict__ out) {
    extern __shared__ float smf[];
    float* Ws = smf;                   // [128][SWROW]
    float* Hs = smf + DIM * SWROW;     // [64][SWROW]

    const int tid   = threadIdx.x;
    const int node0 = blockIdx.x * 64;
    const int wid   = tid >> 5;        // 0..3
    const int lane  = tid & 31;

    // ---- W tile fill (as R9) ----
    for (int i = tid; i < DIM * DIM / 4; i += 128) {
        int o  = i >> 5;
        int k4 = (i & 31) << 2;
        float4 w = __ldg(reinterpret_cast<const float4*>(W) + i);
        float* p = Ws + o * SWROW + k4;
        p[0] = w.x; p[1] = w.y; p[2] = w.z; p[3] = w.w;
    }

    // ---- fused gather-aggregate into Hs: warp handles 16 nodes ----
    const float4* X = reinterpret_cast<const float4*>(x);
    for (int i = 0; i < 16; ++i) {
        int ln   = wid * 16 + i;
        int node = node0 + ln;
        float4 acc = make_float4(0.f, 0.f, 0.f, 0.f);
        if (node < NNODES) {
            acc = __ldg(X + (size_t)node * 32 + lane);   // self term (eps=0)
            int s = g_off[node];
            int e = g_off[node + 1];
            for (int base = s; base < e; base += 32) {
                int idx = base + lane;
                int my  = (idx < e) ? __ldg(g_csr + idx) : 0;
                int nv  = min(32, e - base);
#pragma unroll 4
                for (int j = 0; j < nv; ++j) {
                    int src  = __shfl_sync(0xffffffffu, my, j);
                    float4 v = __ldg(X + (size_t)src * 32 + lane);
                    acc.x += v.x; acc.y += v.y; acc.z += v.z; acc.w += v.w;
                }
            }
        }
        float* p = Hs + ln * SWROW + lane * 4;   // scalar STS (129 stride: ok)
        p[0] = acc.x; p[1] = acc.y; p[2] = acc.z; p[3] = acc.w;
    }
    __syncthreads();

    // ---- compute (R9, measured good) ----
    const int tx = tid >> 3;      // 16 o-groups of 8
    const int ty = tid & 7;       // 8 n-groups of 8
    const int o0 = tx * 8;
    const int n0 = ty * 8;

    const float* Wb = Ws + o0 * SWROW;
    const float* Hb = Hs + n0 * SWROW;

    u64 acc[8][4];
    {
        float4 b0 = __ldg(reinterpret_cast<const float4*>(bias + o0));
        float4 b1 = __ldg(reinterpret_cast<const float4*>(bias + o0 + 4));
        u64 bp[4] = { pk2(b0.x, b0.y), pk2(b0.z, b0.w),
                      pk2(b1.x, b1.y), pk2(b1.z, b1.w) };
#pragma unroll
        for (int i = 0; i < 8; ++i)
#pragma unroll
            for (int j = 0; j < 4; ++j) acc[i][j] = bp[j];
    }

#pragma unroll 4
    for (int k = 0; k < DIM; ++k) {
        float w[8], h[8];
#pragma unroll
        for (int i = 0; i < 8; ++i) w[i] = Wb[i * SWROW + k];
#pragma unroll
        for (int i = 0; i < 8; ++i) h[i] = Hb[i * SWROW + k];
        u64 wp[4] = { pk2(w[0], w[1]), pk2(w[2], w[3]),
                      pk2(w[4], w[5]), pk2(w[6], w[7]) };
#pragma unroll
        for (int i = 0; i < 8; ++i) {
            u64 hd = pk2(h[i], h[i]);
#pragma unroll
            for (int j = 0; j < 4; ++j)
                acc[i][j] = ffma2(hd, wp[j], acc[i][j]);
        }
    }

#pragma unroll
    for (int i = 0; i < 8; ++i) {
        int node = node0 + n0 + i;
        if (node < NNODES) {
            ulonglong2* orow = reinterpret_cast<ulonglong2*>(out + (size_t)node * DIM + o0);
            orow[0] = make_ulonglong2(acc[i][0], acc[i][1]);
            orow[1] = make_ulonglong2(acc[i][2], acc[i][3]);
        }
    }
}

// ---------------------------------------------------------------------------
// Launch. Output tuple (out, hid): d_out[0:N*D)=out, d_out[N*D:2N*D)=hid.
// ---------------------------------------------------------------------------
extern "C" void kernel_launch(void* const* d_in, const int* in_sizes, int n_in,
                              void* d_out, int out_size) {
    const float* x  = (const float*)d_in[0];
    const int*   ei = (const int*)  d_in[1];
    const float* W1 = (const float*)d_in[2];
    const float* b1 = (const float*)d_in[3];
    const float* W2 = (const float*)d_in[4];
    const float* b2 = (const float*)d_in[5];

    float* out = (float*)d_out;
    float* hid = (float*)d_out + (size_t)NNODES * DIM;

    const int smem = (DIM + 64) * SWROW * (int)sizeof(float);   // 99072 B

    static bool attr_set = false;
    if (!attr_set) {
        cudaFuncSetAttribute(gin_layer_kernel,
                             cudaFuncAttributeMaxDynamicSharedMemorySize, smem);
        attr_set = true;
    }

    const int nb_nodes = (NNODES + 255) / 256;
    const int nb_edges = (NEDGES + 255) / 256;
    const int nb_layer = (NNODES + 63) / 64;

    // ---- CSR build (g_deg arrives zeroed: static init / restored by fill) ----
    hist_kernel<<<nb_edges, 256>>>(ei);
    scan1_kernel<<<NBLK, SCANB>>>();
    scan2_kernel<<<1, 128>>>();
    scan3_kernel<<<nb_nodes, 256>>>();
    fill_kernel<<<nb_edges, 256>>>(ei);

    // ---- Layer 1 (fused aggregate + GEMM) ----
    gin_layer_kernel<<<nb_layer, 128, smem>>>(x, W1, b1, hid);

    // ---- Layer 2 ----
    gin_layer_kernel<<<nb_layer, 128, smem>>>(hid, W2, b2, out);
}

// round 16
// speedup vs baseline: 1.6431x; 1.6431x over previous
#include <cuda_runtime.h>
#include <cuda_bf16.h>
#include <cstdint>

#define NNODES 100000
#define NEDGES 1600000
#define DIM    128
#define SCANB  1024
#define NBLK   ((NNODES + SCANB - 1) / SCANB)   // 98
#define SWROW  129                              // smem row stride (mod 32 == 1)

typedef unsigned long long u64;

// ---------------- scratch (alloc-free rule: __device__ globals) -------------
// g_deg: zero-initialized at module load; fill_kernel re-zeroes it each call.
__device__ float g_agg[(size_t)NNODES * DIM];
__device__ int   g_deg[NNODES];
__device__ int   g_incl[NNODES];
__device__ int   g_off[NNODES + 1];
__device__ int   g_cur[NNODES];
__device__ int   g_csr[NEDGES];
__device__ int   g_bsum[128];
__device__ int   g_bofs[128];

// ---------------------------------------------------------------------------
// packed fp32x2 helpers
// ---------------------------------------------------------------------------
__device__ __forceinline__ u64 ffma2(u64 a, u64 b, u64 c) {
    u64 d;
    asm("fma.rn.f32x2 %0, %1, %2, %3;" : "=l"(d) : "l"(a), "l"(b), "l"(c));
    return d;
}
__device__ __forceinline__ u64 pk2(float lo, float hi) {
    u64 r;
    asm("mov.b64 %0, {%1, %2};" : "=l"(r) : "f"(lo), "f"(hi));
    return r;
}

// ---------------------------------------------------------------------------
// CSR build (R9, measured good)
// ---------------------------------------------------------------------------
__global__ void hist_kernel(const int* __restrict__ ei) {
    int e = blockIdx.x * blockDim.x + threadIdx.x;
    if (e < NEDGES) atomicAdd(&g_deg[__ldg(ei + NEDGES + e)], 1);
}

__global__ void scan1_kernel() {
    __shared__ int sm[SCANB];
    int i = blockIdx.x * SCANB + threadIdx.x;
    int v = (i < NNODES) ? g_deg[i] : 0;
    sm[threadIdx.x] = v;
    __syncthreads();
#pragma unroll
    for (int ofs = 1; ofs < SCANB; ofs <<= 1) {
        int t = (threadIdx.x >= ofs) ? sm[threadIdx.x - ofs] : 0;
        __syncthreads();
        sm[threadIdx.x] += t;
        __syncthreads();
    }
    if (i < NNODES) g_incl[i] = sm[threadIdx.x];
    if (threadIdx.x == SCANB - 1) g_bsum[blockIdx.x] = sm[SCANB - 1];
}

__global__ void scan2_kernel() {
    __shared__ int sm[128];
    int t = threadIdx.x;
    int v = (t < NBLK) ? g_bsum[t] : 0;
    sm[t] = v;
    __syncthreads();
#pragma unroll
    for (int ofs = 1; ofs < 128; ofs <<= 1) {
        int u = (t >= ofs) ? sm[t - ofs] : 0;
        __syncthreads();
        sm[t] += u;
        __syncthreads();
    }
    if (t < NBLK) g_bofs[t] = sm[t] - v;    // exclusive
}

__global__ void scan3_kernel() {
    int i = blockIdx.x * blockDim.x + threadIdx.x;
    if (i < NNODES) {
        int off = g_incl[i] - g_deg[i] + g_bofs[i >> 10];
        g_off[i] = off;
        g_cur[i] = off;
    }
    if (i == 0) g_off[NNODES] = NEDGES;
}

__global__ void fill_kernel(const int* __restrict__ ei) {
    int e = blockIdx.x * blockDim.x + threadIdx.x;
    if (e < NEDGES) {
        int dst = __ldg(ei + NEDGES + e);
        int p = atomicAdd(&g_cur[dst], 1);
        g_csr[p] = __ldg(ei + e);
    }
    if (e < NNODES) g_deg[e] = 0;   // restore invariant for next replay
}

// ---------------------------------------------------------------------------
// Aggregation v4: one warp per PAIR of nodes (2p, 2p+1), lane l owns dims
// [4l, 4l+4) as in R6/R9. Both CSR lists iterate in lockstep in one loop:
// per j -> 2 shfl + 2 INDEPENDENT full-warp LDG.128 + 2 independent FADD
// chains. Doubles memory-level parallelism per warp at a cost of one extra
// float4 accumulator (no R7-style register blowup, no R10 row-splitting).
// Sentinel src=-1 predicates the shorter list's tail.
// ---------------------------------------------------------------------------
__global__ __launch_bounds__(256)
void agg_kernel(const float* __restrict__ x) {
    int pair = (blockIdx.x * blockDim.x + threadIdx.x) >> 5;
    int lane = threadIdx.x & 31;
    int w0 = pair * 2;
    int w1 = w0 + 1;
    if (w0 >= NNODES) return;
    const bool has1 = (w1 < NNODES);

    const float4* X = reinterpret_cast<const float4*>(x);
    int s0 = g_off[w0];
    int e0 = g_off[w0 + 1];
    int s1 = has1 ? g_off[w1]     : 0;
    int e1 = has1 ? g_off[w1 + 1] : 0;
    int n0 = e0 - s0;
    int n1 = e1 - s1;
    int nmax = max(n0, n1);

    float4 acc0 = __ldg(X + (size_t)w0 * 32 + lane);           // self term
    float4 acc1 = has1 ? __ldg(X + (size_t)w1 * 32 + lane)
                       : make_float4(0.f, 0.f, 0.f, 0.f);

    for (int base = 0; base < nmax; base += 32) {
        int t   = base + lane;
        int my0 = (t < n0) ? __ldg(g_csr + s0 + t) : -1;
        int my1 = (t < n1) ? __ldg(g_csr + s1 + t) : -1;
        int nv  = min(32, nmax - base);
#pragma unroll 4
        for (int j = 0; j < nv; ++j) {
            int src0 = __shfl_sync(0xffffffffu, my0, j);
            int src1 = __shfl_sync(0xffffffffu, my1, j);
            if (src0 >= 0) {
                float4 v = __ldg(X + (size_t)src0 * 32 + lane);
                acc0.x += v.x; acc0.y += v.y; acc0.z += v.z; acc0.w += v.w;
            }
            if (src1 >= 0) {
                float4 v = __ldg(X + (size_t)src1 * 32 + lane);
                acc1.x += v.x; acc1.y += v.y; acc1.z += v.z; acc1.w += v.w;
            }
        }
    }

    float4* A = reinterpret_cast<float4*>(g_agg);
    A[(size_t)w0 * 32 + lane] = acc0;
    if (has1) A[(size_t)w1 * 32 + lane] = acc1;
}

// ---------------------------------------------------------------------------
// GEMM (R9, measured good): out[n][o] = bias[o] + sum_k H[n][k]*W[o][k]
// 128 thr; 64 nodes x 128 outs; 8x8 register tile; stride-129 smem.
// ---------------------------------------------------------------------------
__global__ __launch_bounds__(128, 2)
void gemm_kernel(const float* __restrict__ H,
                 const float* __restrict__ W,
                 const float* __restrict__ bias,
                 float* __restrict__ out) {
    extern __shared__ float smf[];
    float* Ws = smf;                   // [128][SWROW]
    float* Hs = smf + DIM * SWROW;     // [64][SWROW]

    const int tid   = threadIdx.x;
    const int node0 = blockIdx.x * 64;

    for (int i = tid; i < DIM * DIM / 4; i += 128) {
        int o  = i >> 5;
        int k4 = (i & 31) << 2;
        float4 w = __ldg(reinterpret_cast<const float4*>(W) + i);
        float* p = Ws + o * SWROW + k4;
        p[0] = w.x; p[1] = w.y; p[2] = w.z; p[3] = w.w;
    }
    for (int i = tid; i < 64 * DIM / 4; i += 128) {
        int n  = i >> 5;
        int k4 = (i & 31) << 2;
        int node = node0 + n;
        float4 h = make_float4(0.f, 0.f, 0.f, 0.f);
        if (node < NNODES)
            h = __ldg(reinterpret_cast<const float4*>(H) + (size_t)node * 32 + (k4 >> 2));
        float* p = Hs + n * SWROW + k4;
        p[0] = h.x; p[1] = h.y; p[2] = h.z; p[3] = h.w;
    }
    __syncthreads();

    const int tx = tid >> 3;
    const int ty = tid & 7;
    const int o0 = tx * 8;
    const int n0 = ty * 8;

    const float* Wb = Ws + o0 * SWROW;
    const float* Hb = Hs + n0 * SWROW;

    u64 acc[8][4];
    {
        float4 b0 = __ldg(reinterpret_cast<const float4*>(bias + o0));
        float4 b1 = __ldg(reinterpret_cast<const float4*>(bias + o0 + 4));
        u64 bp[4] = { pk2(b0.x, b0.y), pk2(b0.z, b0.w),
                      pk2(b1.x, b1.y), pk2(b1.z, b1.w) };
#pragma unroll
        for (int i = 0; i < 8; ++i)
#pragma unroll
            for (int j = 0; j < 4; ++j) acc[i][j] = bp[j];
    }

#pragma unroll 4
    for (int k = 0; k < DIM; ++k) {
        float w[8], h[8];
#pragma unroll
        for (int i = 0; i < 8; ++i) w[i] = Wb[i * SWROW + k];
#pragma unroll
        for (int i = 0; i < 8; ++i) h[i] = Hb[i * SWROW + k];
        u64 wp[4] = { pk2(w[0], w[1]), pk2(w[2], w[3]),
                      pk2(w[4], w[5]), pk2(w[6], w[7]) };
#pragma unroll
        for (int i = 0; i < 8; ++i) {
            u64 hd = pk2(h[i], h[i]);
#pragma unroll
            for (int j = 0; j < 4; ++j)
                acc[i][j] = ffma2(hd, wp[j], acc[i][j]);
        }
    }

#pragma unroll
    for (int i = 0; i < 8; ++i) {
        int node = node0 + n0 + i;
        if (node < NNODES) {
            ulonglong2* orow = reinterpret_cast<ulonglong2*>(out + (size_t)node * DIM + o0);
            orow[0] = make_ulonglong2(acc[i][0], acc[i][1]);
            orow[1] = make_ulonglong2(acc[i][2], acc[i][3]);
        }
    }
}

// ---------------------------------------------------------------------------
// Launch. Output tuple (out, hid): d_out[0:N*D)=out, d_out[N*D:2N*D)=hid.
// ---------------------------------------------------------------------------
extern "C" void kernel_launch(void* const* d_in, const int* in_sizes, int n_in,
                              void* d_out, int out_size) {
    const float* x  = (const float*)d_in[0];
    const int*   ei = (const int*)  d_in[1];
    const float* W1 = (const float*)d_in[2];
    const float* b1 = (const float*)d_in[3];
    const float* W2 = (const float*)d_in[4];
    const float* b2 = (const float*)d_in[5];

    float* out = (float*)d_out;
    float* hid = (float*)d_out + (size_t)NNODES * DIM;

    const int smem = (DIM + 64) * SWROW * (int)sizeof(float);   // 99072 B

    static bool attr_set = false;
    if (!attr_set) {
        cudaFuncSetAttribute(gemm_kernel,
                             cudaFuncAttributeMaxDynamicSharedMemorySize, smem);
        attr_set = true;
    }

    float* agg;
    cudaGetSymbolAddress((void**)&agg, g_agg);

    const int nb_nodes = (NNODES + 255) / 256;
    const int nb_edges = (NEDGES + 255) / 256;
    const int npairs   = (NNODES + 1) / 2;
    const int nb_agg   = (npairs * 32 + 255) / 256;   // 1 warp / node-pair
    const int nb_gemm  = (NNODES + 63) / 64;

    // ---- CSR build (g_deg arrives zeroed: static init / restored by fill) ----
    hist_kernel<<<nb_edges, 256>>>(ei);
    scan1_kernel<<<NBLK, SCANB>>>();
    scan2_kernel<<<1, 128>>>();
    scan3_kernel<<<nb_nodes, 256>>>();
    fill_kernel<<<nb_edges, 256>>>(ei);

    // ---- Layer 1 ----
    agg_kernel<<<nb_agg, 256>>>(x);
    gemm_kernel<<<nb_gemm, 128, smem>>>(agg, W1, b1, hid);

    // ---- Layer 2 ----
    agg_kernel<<<nb_agg, 256>>>(hid);
    gemm_kernel<<<nb_gemm, 128, smem>>>(agg, W2, b2, out);
}